// round 7
// baseline (speedup 1.0000x reference)
#include <cuda_runtime.h>
#include <cuda_bf16.h>
#include <cstdint>

// out[row, i, e] = x[row, i] * W[i, e] + b[i, e]
// rows = 16384, i in [0,200), e in [0,64).
//
// Round-5: identical structure to round-4 (STG.E.256, W/b register-resident,
// thread-per-32B chunk, 32-reg full occupancy) but DEFAULT write-back stores
// instead of .cs streaming: let L2 batch dirty-line evictions for the DRAM
// scheduler (dram__cycles_active showed 23% idle -> starvation, not
// saturation). RUNROLL 8 batches stores more densely.

#define N_NUM    200
#define E4       16                   // float4 per feature
#define COLS     (N_NUM * E4)         // 3200 float4 per row
#define CHUNKS   (COLS / 2)           // 1600 32B-chunks per row
#define N_ROWS   16384
#define TPB      64
#define CBLKS    (CHUNKS / TPB)       // 25 column blocks
#define RPB      16                   // rows per block
#define RBLKS    (N_ROWS / RPB)       // 1024 row blocks
#define RUNROLL  8

__device__ __forceinline__ void stg256(void* p, float4 a, float4 b)
{
    asm volatile(
        "st.global.v8.b32 [%0], {%1,%2,%3,%4,%5,%6,%7,%8};"
        :: "l"(p),
           "r"(__float_as_uint(a.x)), "r"(__float_as_uint(a.y)),
           "r"(__float_as_uint(a.z)), "r"(__float_as_uint(a.w)),
           "r"(__float_as_uint(b.x)), "r"(__float_as_uint(b.y)),
           "r"(__float_as_uint(b.z)), "r"(__float_as_uint(b.w))
        : "memory");
}

__global__ __launch_bounds__(TPB, 32)   // force regs<=32: full 2048 thr/SM
void numproj_kernel(const float* __restrict__ x,
                    const float4* __restrict__ W4,
                    const float4* __restrict__ B4,
                    float4* __restrict__ out)
{
    const int c    = blockIdx.x * TPB + threadIdx.x;  // 32B chunk 0..1599
    const int j0   = 2 * c;                           // first float4 column
    const int i    = c >> 3;                          // feature 0..199
    const int row0 = blockIdx.y * RPB;

    // Per-column constants held in registers for all rows.
    const float4 w0 = __ldg(&W4[j0]);
    const float4 w1 = __ldg(&W4[j0 + 1]);
    const float4 b0 = __ldg(&B4[j0]);
    const float4 b1 = __ldg(&B4[j0 + 1]);

    const float* xp = x + (size_t)row0 * N_NUM + i;
    char* op = (char*)(out + (size_t)row0 * COLS + j0);
    const size_t row_bytes = (size_t)COLS * sizeof(float4);

    #pragma unroll 1
    for (int r = 0; r < RPB; r += RUNROLL) {
        float xv[RUNROLL];
        #pragma unroll
        for (int u = 0; u < RUNROLL; ++u)
            xv[u] = __ldg(xp + (size_t)u * N_NUM);

        #pragma unroll
        for (int u = 0; u < RUNROLL; ++u) {
            float4 o0, o1;
            o0.x = fmaf(xv[u], w0.x, b0.x);
            o0.y = fmaf(xv[u], w0.y, b0.y);
            o0.z = fmaf(xv[u], w0.z, b0.z);
            o0.w = fmaf(xv[u], w0.w, b0.w);
            o1.x = fmaf(xv[u], w1.x, b1.x);
            o1.y = fmaf(xv[u], w1.y, b1.y);
            o1.z = fmaf(xv[u], w1.z, b1.z);
            o1.w = fmaf(xv[u], w1.w, b1.w);
            stg256(op + (size_t)u * row_bytes, o0, o1);
        }
        xp += (size_t)RUNROLL * N_NUM;
        op += (size_t)RUNROLL * row_bytes;
    }
}

extern "C" void kernel_launch(void* const* d_in, const int* in_sizes, int n_in,
                              void* d_out, int out_size)
{
    const float*  x  = (const float*) d_in[0];   // [16384, 200] f32
    const float4* W4 = (const float4*)d_in[1];   // [200, 64] f32 -> 3200 float4
    const float4* B4 = (const float4*)d_in[2];
    float4* out = (float4*)d_out;

    dim3 grid(CBLKS, RBLKS);   // 25 x 1024 blocks
    numproj_kernel<<<grid, TPB>>>(x, W4, B4, out);
}

// round 8
// speedup vs baseline: 1.0144x; 1.0144x over previous
#include <cuda_runtime.h>
#include <cuda_bf16.h>
#include <cstdint>

// out[row, i, e] = x[row, i] * W[i, e] + b[i, e]
// rows = 16384, i in [0,200), e in [0,64).
//
// Round-6: test the last untried hypothesis — DRAM page locality. 320-thread
// blocks write 10KB fully-contiguous bursts per iteration (vs 2KB before),
// giving the DRAM scheduler longer same-page runs. Everything else as the
// best variant: STG.E.256 .cs, W/b register-resident, thread-per-32B chunk.

#define N_NUM    200
#define E4       16                   // float4 per feature
#define COLS     (N_NUM * E4)         // 3200 float4 per row
#define CHUNKS   (COLS / 2)           // 1600 32B-chunks per row
#define N_ROWS   16384
#define TPB      320                  // 10 warps -> 10KB contiguous per iter
#define CBLKS    (CHUNKS / TPB)       // 5 column blocks
#define RPB      16                   // rows per block
#define RBLKS    (N_ROWS / RPB)       // 1024 row blocks
#define RUNROLL  4

__device__ __forceinline__ void stg256_cs(void* p, float4 a, float4 b)
{
    asm volatile(
        "st.global.cs.v8.b32 [%0], {%1,%2,%3,%4,%5,%6,%7,%8};"
        :: "l"(p),
           "r"(__float_as_uint(a.x)), "r"(__float_as_uint(a.y)),
           "r"(__float_as_uint(a.z)), "r"(__float_as_uint(a.w)),
           "r"(__float_as_uint(b.x)), "r"(__float_as_uint(b.y)),
           "r"(__float_as_uint(b.z)), "r"(__float_as_uint(b.w))
        : "memory");
}

__global__ __launch_bounds__(TPB, 6)   // keep regs<=32: 6x320 = 1920 thr/SM
void numproj_kernel(const float* __restrict__ x,
                    const float4* __restrict__ W4,
                    const float4* __restrict__ B4,
                    float4* __restrict__ out)
{
    const int c    = blockIdx.x * TPB + threadIdx.x;  // 32B chunk 0..1599
    const int j0   = 2 * c;                           // first float4 column
    const int i    = c >> 3;                          // feature 0..199
    const int row0 = blockIdx.y * RPB;

    // Per-column constants held in registers for all rows.
    const float4 w0 = __ldg(&W4[j0]);
    const float4 w1 = __ldg(&W4[j0 + 1]);
    const float4 b0 = __ldg(&B4[j0]);
    const float4 b1 = __ldg(&B4[j0 + 1]);

    const float* xp = x + (size_t)row0 * N_NUM + i;
    char* op = (char*)(out + (size_t)row0 * COLS + j0);
    const size_t row_bytes = (size_t)COLS * sizeof(float4);

    #pragma unroll 1
    for (int r = 0; r < RPB; r += RUNROLL) {
        float xv[RUNROLL];
        #pragma unroll
        for (int u = 0; u < RUNROLL; ++u)
            xv[u] = __ldg(xp + (size_t)u * N_NUM);

        #pragma unroll
        for (int u = 0; u < RUNROLL; ++u) {
            float4 o0, o1;
            o0.x = fmaf(xv[u], w0.x, b0.x);
            o0.y = fmaf(xv[u], w0.y, b0.y);
            o0.z = fmaf(xv[u], w0.z, b0.z);
            o0.w = fmaf(xv[u], w0.w, b0.w);
            o1.x = fmaf(xv[u], w1.x, b1.x);
            o1.y = fmaf(xv[u], w1.y, b1.y);
            o1.z = fmaf(xv[u], w1.z, b1.z);
            o1.w = fmaf(xv[u], w1.w, b1.w);
            stg256_cs(op + (size_t)u * row_bytes, o0, o1);
        }
        xp += (size_t)RUNROLL * N_NUM;
        op += (size_t)RUNROLL * row_bytes;
    }
}

extern "C" void kernel_launch(void* const* d_in, const int* in_sizes, int n_in,
                              void* d_out, int out_size)
{
    const float*  x  = (const float*) d_in[0];   // [16384, 200] f32
    const float4* W4 = (const float4*)d_in[1];   // [200, 64] f32 -> 3200 float4
    const float4* B4 = (const float4*)d_in[2];
    float4* out = (float4*)d_out;

    dim3 grid(CBLKS, RBLKS);   // 5 x 1024 blocks
    numproj_kernel<<<grid, TPB>>>(x, W4, B4, out);
}